// round 3
// baseline (speedup 1.0000x reference)
#include <cuda_runtime.h>
#include <math.h>

#define ORD  2048
#define INDIM 64
#define TLEN 4096
#define NC   256

typedef unsigned long long ull;

// ---------------- static device scratch (allocation-free) ----------------
__device__ float g_E0[ORD * 4096];   // BU tree level 0: col = j*256 + c
__device__ float g_E1[ORD * 2048];
__device__ float g_E2[ORD * 1024];
__device__ float g_E3[ORD * 512];
__device__ float g_D [ORD * 256];
__device__ float g_Q2 [ORD * ORD];
__device__ float g_Q4 [ORD * ORD];
__device__ float g_Q8 [ORD * ORD];
__device__ float g_Q16[ORD * ORD];
__device__ float g_S  [ORD * 4096];  // states, col = j*256 + c
__device__ float g_Bnd[ORD * 256];   // chunk boundary states b_c
__device__ float g_part[4 * ORD * 512];
__device__ float g_bv[2 * ORD];
__device__ unsigned int g_bar_count;
__device__ volatile unsigned int g_bar_gen;

// ---------------- packed f32x2 helpers ----------------
__device__ __forceinline__ ull fma2(ull a, ull b, ull c) {
    ull d;
    asm("fma.rn.f32x2 %0, %1, %2, %3;" : "=l"(d) : "l"(a), "l"(b), "l"(c));
    return d;
}
__device__ __forceinline__ ull dup2(float x) {
    ull d;
    asm("mov.b64 %0, {%1, %1};" : "=l"(d) : "f"(x));
    return d;
}
__device__ __forceinline__ float2 unpk(ull v) {
    float2 f;
    asm("mov.b64 {%0, %1}, %2;" : "=f"(f.x), "=f"(f.y) : "l"(v));
    return f;
}

// ---------------- single-wave spin grid barrier ----------------
__device__ __forceinline__ void grid_barrier(unsigned int nb) {
    __syncthreads();
    if (threadIdx.x == 0) {
        __threadfence();
        unsigned int gen = g_bar_gen;
        if (atomicAdd(&g_bar_count, 1u) == nb - 1u) {
            g_bar_count = 0u;
            __threadfence();
            g_bar_gen = gen + 1u;
        } else {
            while (g_bar_gen == gen) { __nanosleep(32); }
        }
        __threadfence();
    }
    __syncthreads();
}

// ---------------- BU precompute: E0[r][j*256+c] = (B@u)[r, t=c*16+j] -------
__global__ void bu_kernel(const float* __restrict__ B, const float* __restrict__ u,
                          float* __restrict__ E0) {
    int t = blockIdx.x * 32 + threadIdx.x;   // blockDim (32,8)
    int r = blockIdx.y * 8 + threadIdx.y;
    float s = 0.f;
#pragma unroll
    for (int d = 0; d < INDIM; d++)
        s += B[r * INDIM + d] * u[d * TLEN + t];
    E0[(size_t)r * 4096 + (t & 15) * 256 + (t >> 4)] = s;
}

// ---------------- generalized SGEMM with block-remapped operands -----------
// C_block(d) = A @ B_block(bmul*d+boff) [+ E_block(amul*d+aoff)] over 256-col
// blocks (tiles BN=128 never cross a block). If gridDim.z>1: write raw
// partials to `part` (reduce kernel applies addend/dst/emit).
// Optional tanh emission to outp at t = c*16 + jdst.
__global__ void __launch_bounds__(256, 2) gemm128(
    const float* __restrict__ A,
    const float* __restrict__ Bm, int ldb, int bmul, int boff,
    float* __restrict__ C, int ldc, int dmul, int doff,
    const float* __restrict__ E, int lde, int amul, int aoff,
    float* __restrict__ outp, float* __restrict__ part,
    int N, int KS)
{
    __shared__ float As[16][132];   // transposed A tile, padded
    __shared__ float Bs[16][128];

    int tid = threadIdx.x;
    int bm = blockIdx.y * 128, bn = blockIdx.x * 128;
    int kbase = blockIdx.z * KS;
    int dblk = bn >> 8, w = bn & 255;

    const float* Ap = A + (size_t)bm * ORD + kbase;
    const float* Bp = Bm + (size_t)kbase * ldb + (size_t)(bmul * dblk + boff) * 256 + w;

    int arow = tid >> 2, acol = (tid & 3) * 4;
    int brow = tid >> 5, bcol = (tid & 31) * 4;
    int tn = (tid & 15) * 8, tm = (tid >> 4) * 8;

    ull acc[8][4];
#pragma unroll
    for (int i = 0; i < 8; i++)
#pragma unroll
        for (int j = 0; j < 4; j++) acc[i][j] = 0ull;

    float4 pa0 = *(const float4*)&Ap[(size_t)arow * ORD + acol];
    float4 pa1 = *(const float4*)&Ap[(size_t)(arow + 64) * ORD + acol];
    float4 pb0 = *(const float4*)&Bp[(size_t)brow * ldb + bcol];
    float4 pb1 = *(const float4*)&Bp[(size_t)(brow + 8) * ldb + bcol];

    int ntiles = KS / 16;
    for (int t = 0; t < ntiles; t++) {
        As[acol + 0][arow] = pa0.x; As[acol + 1][arow] = pa0.y;
        As[acol + 2][arow] = pa0.z; As[acol + 3][arow] = pa0.w;
        As[acol + 0][arow + 64] = pa1.x; As[acol + 1][arow + 64] = pa1.y;
        As[acol + 2][arow + 64] = pa1.z; As[acol + 3][arow + 64] = pa1.w;
        *(float4*)&Bs[brow][bcol] = pb0;
        *(float4*)&Bs[brow + 8][bcol] = pb1;
        __syncthreads();

        if (t + 1 < ntiles) {
            Ap += 16; Bp += (size_t)16 * ldb;
            pa0 = *(const float4*)&Ap[(size_t)arow * ORD + acol];
            pa1 = *(const float4*)&Ap[(size_t)(arow + 64) * ORD + acol];
            pb0 = *(const float4*)&Bp[(size_t)brow * ldb + bcol];
            pb1 = *(const float4*)&Bp[(size_t)(brow + 8) * ldb + bcol];
        }

#pragma unroll
        for (int k = 0; k < 16; k++) {
            float4 a0 = *(const float4*)&As[k][tm];
            float4 a1 = *(const float4*)&As[k][tm + 4];
            ulonglong2 q0 = *(const ulonglong2*)&Bs[k][tn];
            ulonglong2 q1 = *(const ulonglong2*)&Bs[k][tn + 4];
            float av[8] = {a0.x, a0.y, a0.z, a0.w, a1.x, a1.y, a1.z, a1.w};
#pragma unroll
            for (int i = 0; i < 8; i++) {
                ull ad = dup2(av[i]);
                acc[i][0] = fma2(ad, q0.x, acc[i][0]);
                acc[i][1] = fma2(ad, q0.y, acc[i][1]);
                acc[i][2] = fma2(ad, q1.x, acc[i][2]);
                acc[i][3] = fma2(ad, q1.y, acc[i][3]);
            }
        }
        __syncthreads();
    }

    if (gridDim.z > 1) {
        float* Cp = part + (size_t)blockIdx.z * ORD * N + (size_t)(bm + tm) * N + bn + tn;
#pragma unroll
        for (int i = 0; i < 8; i++) {
            float2 v0 = unpk(acc[i][0]), v1 = unpk(acc[i][1]);
            float2 v2 = unpk(acc[i][2]), v3 = unpk(acc[i][3]);
            *(float4*)&Cp[(size_t)i * N]     = make_float4(v0.x, v0.y, v1.x, v1.y);
            *(float4*)&Cp[(size_t)i * N + 4] = make_float4(v2.x, v2.y, v3.x, v3.y);
        }
        return;
    }

    int jdst = dmul * dblk + doff;
    int c0 = w + tn;
    float* Cp = C + (size_t)(bm + tm) * ldc + (size_t)jdst * 256 + c0;
    const float* Ep = E ? E + (size_t)(bm + tm) * lde + (size_t)(amul * dblk + aoff) * 256 + c0
                        : (const float*)0;
#pragma unroll
    for (int i = 0; i < 8; i++) {
        float2 v0 = unpk(acc[i][0]), v1 = unpk(acc[i][1]);
        float2 v2 = unpk(acc[i][2]), v3 = unpk(acc[i][3]);
        float v[8] = {v0.x, v0.y, v1.x, v1.y, v2.x, v2.y, v3.x, v3.y};
        if (Ep) {
#pragma unroll
            for (int k = 0; k < 8; k++) v[k] += Ep[(size_t)i * lde + k];
        }
        *(float4*)&Cp[(size_t)i * ldc]     = make_float4(v[0], v[1], v[2], v[3]);
        *(float4*)&Cp[(size_t)i * ldc + 4] = make_float4(v[4], v[5], v[6], v[7]);
        if (outp) {
            float* op = outp + (size_t)(bm + tm + i) * 4096 + jdst;
#pragma unroll
            for (int k = 0; k < 8; k++) op[(c0 + k) * 16] = tanhf(v[k]);
        }
    }
}

// ---------------- split-K reduce: sum slabs + addend + remap dst (+emit) ---
__global__ void reduce_k(const float* __restrict__ part, int N, int z,
                         const float* __restrict__ E, int lde, int amul, int aoff,
                         float* __restrict__ C, int ldc, int dmul, int doff,
                         float* __restrict__ outp) {
    int idx = blockIdx.x * 256 + threadIdx.x;   // over ORD*N
    int r = idx / N, n = idx - r * N;
    float v = 0.f;
    for (int s = 0; s < z; s++) v += part[(size_t)s * ORD * N + idx];
    int d = n >> 8, cc = n & 255;
    v += E[(size_t)r * lde + (size_t)(amul * d + aoff) * 256 + cc];
    int j = dmul * d + doff;
    C[(size_t)r * ldc + (size_t)j * 256 + cc] = v;
    if (outp) outp[(size_t)r * 4096 + cc * 16 + j] = tanhf(v);
}

// ---------------- persistent boundary scan: b_{c+1} = A16 b_c + D_c --------
// Also writes S block 0 (s_0 = b_c) and emits tanh(b_c) at t = c*16.
__global__ void __launch_bounds__(256, 1) scan_kernel(
    const float* __restrict__ A16, const float* __restrict__ D,
    float* __restrict__ Bnd, float* __restrict__ S, float* __restrict__ outp)
{
    __shared__ float bs[ORD];
    __shared__ float red[16][9];

    int tid = threadIdx.x;
    int cta = blockIdx.x;                 // 128 CTAs, 16 rows each
    int rloc = tid & 15;
    int row = cta * 16 + rloc;
    int seg = (tid >> 4) * 128;

    ulonglong2 a2[32];
    const ulonglong2* Arow = (const ulonglong2*)(A16 + (size_t)row * ORD + seg);
#pragma unroll
    for (int i = 0; i < 32; i++) a2[i] = Arow[i];

    for (int i = tid; i < ORD; i += 256) g_bv[i] = 1.0f;
    if (tid < 16) {
        int rr = cta * 16 + tid;
        Bnd[(size_t)rr * 256 + 0] = 1.0f;
        S[(size_t)rr * 4096 + 0] = 1.0f;
        outp[(size_t)rr * 4096 + 0] = tanhf(1.0f);
    }
    grid_barrier(128);

    for (int c = 0; c < NC - 1; c++) {
        const float4* bsrc = (const float4*)(g_bv + (c & 1) * ORD);
        float4* bdst4 = (float4*)bs;
        bdst4[tid] = bsrc[tid];
        bdst4[tid + 256] = bsrc[tid + 256];
        __syncthreads();

        ull pA = 0ull, pB = 0ull;
        const ulonglong2* b2 = (const ulonglong2*)(bs + seg);
#pragma unroll
        for (int i = 0; i < 32; i++) {
            pA = fma2(a2[i].x, b2[i].x, pA);
            pB = fma2(a2[i].y, b2[i].y, pB);
        }
        float2 fa = unpk(pA), fb = unpk(pB);
        float p = (fa.x + fa.y) + (fb.x + fb.y);
        p += __shfl_down_sync(0xffffffffu, p, 16);
        if ((tid & 31) < 16) red[rloc][tid >> 5] = p;
        __syncthreads();

        if (tid < 16) {
            int rr = cta * 16 + tid;
            float s = red[tid][0] + red[tid][1] + red[tid][2] + red[tid][3]
                    + red[tid][4] + red[tid][5] + red[tid][6] + red[tid][7]
                    + D[(size_t)rr * 256 + c];
            g_bv[((c + 1) & 1) * ORD + rr] = s;
            Bnd[(size_t)rr * 256 + c + 1] = s;
            S[(size_t)rr * 4096 + c + 1] = s;
            outp[(size_t)rr * 4096 + (c + 1) * 16] = tanhf(s);
        }
        grid_barrier(128);
    }
}

// ---------------- host orchestration ----------------
extern "C" void kernel_launch(void* const* d_in, const int* in_sizes, int n_in,
                              void* d_out, int out_size) {
    const float* u = 0; const float* wa = 0; const float* wb = 0;
    for (int i = 0; i < n_in; i++) {
        if (in_sizes[i] == INDIM * TLEN)       u  = (const float*)d_in[i];
        else if (in_sizes[i] == ORD * ORD)     wa = (const float*)d_in[i];
        else if (in_sizes[i] == ORD * INDIM)   wb = (const float*)d_in[i];
    }
    float* out = (float*)d_out;

    float *E0, *E1, *E2, *E3, *D, *Q2, *Q4, *Q8, *Q16, *S, *Bnd, *part;
    cudaGetSymbolAddress((void**)&E0, g_E0);
    cudaGetSymbolAddress((void**)&E1, g_E1);
    cudaGetSymbolAddress((void**)&E2, g_E2);
    cudaGetSymbolAddress((void**)&E3, g_E3);
    cudaGetSymbolAddress((void**)&D,  g_D);
    cudaGetSymbolAddress((void**)&Q2, g_Q2);
    cudaGetSymbolAddress((void**)&Q4, g_Q4);
    cudaGetSymbolAddress((void**)&Q8, g_Q8);
    cudaGetSymbolAddress((void**)&Q16, g_Q16);
    cudaGetSymbolAddress((void**)&S,  g_S);
    cudaGetSymbolAddress((void**)&Bnd, g_Bnd);
    cudaGetSymbolAddress((void**)&part, g_part);

    // 1) BU tree level 0
    bu_kernel<<<dim3(TLEN / 32, ORD / 8), dim3(32, 8)>>>(wb, u, E0);

    // 2) squarings: A^2, A^4, A^8, A^16
    gemm128<<<dim3(16, 16, 1), 256>>>(wa, wa, ORD, 1, 0, Q2,  ORD, 1, 0,
                                      0, 0, 0, 0, 0, part, 2048, 2048);
    gemm128<<<dim3(16, 16, 1), 256>>>(Q2, Q2, ORD, 1, 0, Q4,  ORD, 1, 0,
                                      0, 0, 0, 0, 0, part, 2048, 2048);
    gemm128<<<dim3(16, 16, 1), 256>>>(Q4, Q4, ORD, 1, 0, Q8,  ORD, 1, 0,
                                      0, 0, 0, 0, 0, part, 2048, 2048);
    gemm128<<<dim3(16, 16, 1), 256>>>(Q8, Q8, ORD, 1, 0, Q16, ORD, 1, 0,
                                      0, 0, 0, 0, 0, part, 2048, 2048);

    // 3) upsweep: E1 = A*E0even + E0odd; E2 = A2*E1even + E1odd; ...
    gemm128<<<dim3(16, 16, 1), 256>>>(wa, E0, 4096, 2, 0, E1, 2048, 1, 0,
                                      E0, 4096, 2, 1, 0, part, 2048, 2048);
    gemm128<<<dim3(8, 16, 1), 256>>>(Q2, E1, 2048, 2, 0, E2, 1024, 1, 0,
                                     E1, 2048, 2, 1, 0, part, 1024, 2048);
    gemm128<<<dim3(4, 16, 2), 256>>>(Q4, E2, 1024, 2, 0, 0, 0, 0, 0,
                                     0, 0, 0, 0, 0, part, 512, 1024);
    reduce_k<<<ORD * 512 / 256, 256>>>(part, 512, 2, E2, 1024, 2, 1,
                                       E3, 512, 1, 0, 0);
    gemm128<<<dim3(2, 16, 4), 256>>>(Q8, E3, 512, 2, 0, 0, 0, 0, 0,
                                     0, 0, 0, 0, 0, part, 256, 512);
    reduce_k<<<ORD * 256 / 256, 256>>>(part, 256, 4, E3, 512, 2, 1,
                                       D, 256, 1, 0, 0);

    // 4) serial boundary scan (emits j=0, fills S block 0 and Bnd)
    scan_kernel<<<128, 256>>>(Q16, D, Bnd, S, out);

    // 5) downsweep: s8 = A8*s0 + E3_0; [s4,s12] = A4*[s0,s8] + [E2_0,E2_2]; ...
    gemm128<<<dim3(2, 16, 4), 256>>>(Q8, Bnd, 256, 1, 0, 0, 0, 0, 0,
                                     0, 0, 0, 0, 0, part, 256, 512);
    reduce_k<<<ORD * 256 / 256, 256>>>(part, 256, 4, E3, 512, 2, 0,
                                       S, 4096, 0, 8, out);
    gemm128<<<dim3(4, 16, 2), 256>>>(Q4, S, 4096, 8, 0, 0, 0, 0, 0,
                                     0, 0, 0, 0, 0, part, 512, 1024);
    reduce_k<<<ORD * 512 / 256, 256>>>(part, 512, 2, E2, 1024, 2, 0,
                                       S, 4096, 8, 4, out);
    gemm128<<<dim3(8, 16, 1), 256>>>(Q2, S, 4096, 4, 0, S, 4096, 4, 2,
                                     E1, 2048, 2, 0, out, part, 1024, 2048);
    gemm128<<<dim3(16, 16, 1), 256>>>(wa, S, 4096, 2, 0, S, 4096, 2, 1,
                                      E0, 4096, 2, 0, out, part, 2048, 2048);
}

// round 4
// speedup vs baseline: 1.5952x; 1.5952x over previous
#include <cuda_runtime.h>
#include <math.h>

#define ORD  2048
#define INDIM 64
#define TLEN 4096
#define NC   256

typedef unsigned long long ull;

// ---------------- static device scratch (allocation-free) ----------------
__device__ float g_E0[ORD * 4096];   // BU tree level 0: col = j*256 + c
__device__ float g_E1[ORD * 2048];
__device__ float g_E2[ORD * 1024];
__device__ float g_E3[ORD * 512];
__device__ float g_D [ORD * 256];
__device__ float g_Q2 [ORD * ORD];
__device__ float g_Q4 [ORD * ORD];
__device__ float g_Q8 [ORD * ORD];
__device__ float g_Q16[ORD * ORD];
__device__ float g_S  [ORD * 4096];  // states, col = j*256 + c
__device__ float g_Bnd[ORD * 256];   // chunk boundary states b_c
__device__ float g_part[4 * ORD * 512];
__device__ float g_bv[2 * ORD];
__device__ unsigned int g_bar_count;
__device__ volatile unsigned int g_bar_gen;

// ---------------- packed f32x2 helpers ----------------
__device__ __forceinline__ ull fma2(ull a, ull b, ull c) {
    ull d;
    asm("fma.rn.f32x2 %0, %1, %2, %3;" : "=l"(d) : "l"(a), "l"(b), "l"(c));
    return d;
}
__device__ __forceinline__ ull dup2(float x) {
    ull d;
    asm("mov.b64 %0, {%1, %1};" : "=l"(d) : "f"(x));
    return d;
}
__device__ __forceinline__ float2 unpk(ull v) {
    float2 f;
    asm("mov.b64 {%0, %1}, %2;" : "=f"(f.x), "=f"(f.y) : "l"(v));
    return f;
}

// ---------------- single-wave spin grid barrier ----------------
__device__ __forceinline__ void grid_barrier(unsigned int nb) {
    __syncthreads();
    if (threadIdx.x == 0) {
        __threadfence();
        unsigned int gen = g_bar_gen;
        if (atomicAdd(&g_bar_count, 1u) == nb - 1u) {
            g_bar_count = 0u;
            __threadfence();
            g_bar_gen = gen + 1u;
        } else {
            while (g_bar_gen == gen) { __nanosleep(32); }
        }
        __threadfence();
    }
    __syncthreads();
}

// ---------------- BU precompute: E0[r][j*256+c] = (B@u)[r, t=c*16+j] -------
__global__ void bu_kernel(const float* __restrict__ B, const float* __restrict__ u,
                          float* __restrict__ E0) {
    int t = blockIdx.x * 32 + threadIdx.x;   // blockDim (32,8)
    int r = blockIdx.y * 8 + threadIdx.y;
    float s = 0.f;
#pragma unroll
    for (int d = 0; d < INDIM; d++)
        s += B[r * INDIM + d] * u[d * TLEN + t];
    E0[(size_t)r * 4096 + (t & 15) * 256 + (t >> 4)] = s;
}

// ---------------- generalized SGEMM with block-remapped operands -----------
// C_block(d) = A @ B_block(bmul*d+boff) [+ E_block(amul*d+aoff)] over 256-col
// blocks (tiles BN=128 never cross a block). If gridDim.z>1: write raw
// partials to `part` (reduce kernel applies addend/dst/emit).
// Optional tanh emission to outp at t = c*16 + jdst.
__global__ void __launch_bounds__(256, 2) gemm128(
    const float* __restrict__ A,
    const float* __restrict__ Bm, int ldb, int bmul, int boff,
    float* __restrict__ C, int ldc, int dmul, int doff,
    const float* __restrict__ E, int lde, int amul, int aoff,
    float* __restrict__ outp, float* __restrict__ part,
    int N, int KS)
{
    __shared__ float As[16][132];   // transposed A tile, padded
    __shared__ float Bs[16][128];

    int tid = threadIdx.x;
    int bm = blockIdx.y * 128, bn = blockIdx.x * 128;
    int kbase = blockIdx.z * KS;
    int dblk = bn >> 8, w = bn & 255;

    const float* Ap = A + (size_t)bm * ORD + kbase;
    const float* Bp = Bm + (size_t)kbase * ldb + (size_t)(bmul * dblk + boff) * 256 + w;

    int arow = tid >> 2, acol = (tid & 3) * 4;
    int brow = tid >> 5, bcol = (tid & 31) * 4;
    int tn = (tid & 15) * 8, tm = (tid >> 4) * 8;

    ull acc[8][4];
#pragma unroll
    for (int i = 0; i < 8; i++)
#pragma unroll
        for (int j = 0; j < 4; j++) acc[i][j] = 0ull;

    float4 pa0 = *(const float4*)&Ap[(size_t)arow * ORD + acol];
    float4 pa1 = *(const float4*)&Ap[(size_t)(arow + 64) * ORD + acol];
    float4 pb0 = *(const float4*)&Bp[(size_t)brow * ldb + bcol];
    float4 pb1 = *(const float4*)&Bp[(size_t)(brow + 8) * ldb + bcol];

    int ntiles = KS / 16;
    for (int t = 0; t < ntiles; t++) {
        As[acol + 0][arow] = pa0.x; As[acol + 1][arow] = pa0.y;
        As[acol + 2][arow] = pa0.z; As[acol + 3][arow] = pa0.w;
        As[acol + 0][arow + 64] = pa1.x; As[acol + 1][arow + 64] = pa1.y;
        As[acol + 2][arow + 64] = pa1.z; As[acol + 3][arow + 64] = pa1.w;
        *(float4*)&Bs[brow][bcol] = pb0;
        *(float4*)&Bs[brow + 8][bcol] = pb1;
        __syncthreads();

        if (t + 1 < ntiles) {
            Ap += 16; Bp += (size_t)16 * ldb;
            pa0 = *(const float4*)&Ap[(size_t)arow * ORD + acol];
            pa1 = *(const float4*)&Ap[(size_t)(arow + 64) * ORD + acol];
            pb0 = *(const float4*)&Bp[(size_t)brow * ldb + bcol];
            pb1 = *(const float4*)&Bp[(size_t)(brow + 8) * ldb + bcol];
        }

#pragma unroll
        for (int k = 0; k < 16; k++) {
            float4 a0 = *(const float4*)&As[k][tm];
            float4 a1 = *(const float4*)&As[k][tm + 4];
            ulonglong2 q0 = *(const ulonglong2*)&Bs[k][tn];
            ulonglong2 q1 = *(const ulonglong2*)&Bs[k][tn + 4];
            float av[8] = {a0.x, a0.y, a0.z, a0.w, a1.x, a1.y, a1.z, a1.w};
#pragma unroll
            for (int i = 0; i < 8; i++) {
                ull ad = dup2(av[i]);
                acc[i][0] = fma2(ad, q0.x, acc[i][0]);
                acc[i][1] = fma2(ad, q0.y, acc[i][1]);
                acc[i][2] = fma2(ad, q1.x, acc[i][2]);
                acc[i][3] = fma2(ad, q1.y, acc[i][3]);
            }
        }
        __syncthreads();
    }

    if (gridDim.z > 1) {
        float* Cp = part + (size_t)blockIdx.z * ORD * N + (size_t)(bm + tm) * N + bn + tn;
#pragma unroll
        for (int i = 0; i < 8; i++) {
            float2 v0 = unpk(acc[i][0]), v1 = unpk(acc[i][1]);
            float2 v2 = unpk(acc[i][2]), v3 = unpk(acc[i][3]);
            *(float4*)&Cp[(size_t)i * N]     = make_float4(v0.x, v0.y, v1.x, v1.y);
            *(float4*)&Cp[(size_t)i * N + 4] = make_float4(v2.x, v2.y, v3.x, v3.y);
        }
        return;
    }

    int jdst = dmul * dblk + doff;
    int c0 = w + tn;
    float* Cp = C + (size_t)(bm + tm) * ldc + (size_t)jdst * 256 + c0;
    const float* Ep = E ? E + (size_t)(bm + tm) * lde + (size_t)(amul * dblk + aoff) * 256 + c0
                        : (const float*)0;
#pragma unroll
    for (int i = 0; i < 8; i++) {
        float2 v0 = unpk(acc[i][0]), v1 = unpk(acc[i][1]);
        float2 v2 = unpk(acc[i][2]), v3 = unpk(acc[i][3]);
        float v[8] = {v0.x, v0.y, v1.x, v1.y, v2.x, v2.y, v3.x, v3.y};
        if (Ep) {
#pragma unroll
            for (int k = 0; k < 8; k++) v[k] += Ep[(size_t)i * lde + k];
        }
        *(float4*)&Cp[(size_t)i * ldc]     = make_float4(v[0], v[1], v[2], v[3]);
        *(float4*)&Cp[(size_t)i * ldc + 4] = make_float4(v[4], v[5], v[6], v[7]);
        if (outp) {
            float* op = outp + (size_t)(bm + tm + i) * 4096 + jdst;
#pragma unroll
            for (int k = 0; k < 8; k++) op[(c0 + k) * 16] = tanhf(v[k]);
        }
    }
}

// ---------------- split-K reduce: sum slabs + addend + remap dst (+emit) ---
__global__ void reduce_k(const float* __restrict__ part, int N, int z,
                         const float* __restrict__ E, int lde, int amul, int aoff,
                         float* __restrict__ C, int ldc, int dmul, int doff,
                         float* __restrict__ outp) {
    int idx = blockIdx.x * 256 + threadIdx.x;   // over ORD*N
    int r = idx / N, n = idx - r * N;
    float v = 0.f;
    for (int s = 0; s < z; s++) v += part[(size_t)s * ORD * N + idx];
    int d = n >> 8, cc = n & 255;
    v += E[(size_t)r * lde + (size_t)(amul * d + aoff) * 256 + cc];
    int j = dmul * d + doff;
    C[(size_t)r * ldc + (size_t)j * 256 + cc] = v;
    if (outp) outp[(size_t)r * 4096 + cc * 16 + j] = tanhf(v);
}

// ---------------- persistent boundary scan: b_{c+1} = A16 b_c + D_c --------
// Also writes S block 0 (s_0 = b_c) and emits tanh(b_c) at t = c*16.
__global__ void __launch_bounds__(256, 1) scan_kernel(
    const float* __restrict__ A16, const float* __restrict__ D,
    float* __restrict__ Bnd, float* __restrict__ S, float* __restrict__ outp)
{
    __shared__ float bs[ORD];
    __shared__ float red[16][9];

    int tid = threadIdx.x;
    int cta = blockIdx.x;                 // 128 CTAs, 16 rows each
    int rloc = tid & 15;
    int row = cta * 16 + rloc;
    int seg = (tid >> 4) * 128;

    ulonglong2 a2[32];
    const ulonglong2* Arow = (const ulonglong2*)(A16 + (size_t)row * ORD + seg);
#pragma unroll
    for (int i = 0; i < 32; i++) a2[i] = Arow[i];

    for (int i = tid; i < ORD; i += 256) g_bv[i] = 1.0f;
    if (tid < 16) {
        int rr = cta * 16 + tid;
        Bnd[(size_t)rr * 256 + 0] = 1.0f;
        S[(size_t)rr * 4096 + 0] = 1.0f;
        outp[(size_t)rr * 4096 + 0] = tanhf(1.0f);
    }
    grid_barrier(128);

    for (int c = 0; c < NC - 1; c++) {
        const float4* bsrc = (const float4*)(g_bv + (c & 1) * ORD);
        float4* bdst4 = (float4*)bs;
        bdst4[tid] = bsrc[tid];
        bdst4[tid + 256] = bsrc[tid + 256];
        __syncthreads();

        ull pA = 0ull, pB = 0ull;
        const ulonglong2* b2 = (const ulonglong2*)(bs + seg);
#pragma unroll
        for (int i = 0; i < 32; i++) {
            pA = fma2(a2[i].x, b2[i].x, pA);
            pB = fma2(a2[i].y, b2[i].y, pB);
        }
        float2 fa = unpk(pA), fb = unpk(pB);
        float p = (fa.x + fa.y) + (fb.x + fb.y);
        p += __shfl_down_sync(0xffffffffu, p, 16);
        if ((tid & 31) < 16) red[rloc][tid >> 5] = p;
        __syncthreads();

        if (tid < 16) {
            int rr = cta * 16 + tid;
            float s = red[tid][0] + red[tid][1] + red[tid][2] + red[tid][3]
                    + red[tid][4] + red[tid][5] + red[tid][6] + red[tid][7]
                    + D[(size_t)rr * 256 + c];
            g_bv[((c + 1) & 1) * ORD + rr] = s;
            Bnd[(size_t)rr * 256 + c + 1] = s;
            S[(size_t)rr * 4096 + c + 1] = s;
            outp[(size_t)rr * 4096 + (c + 1) * 16] = tanhf(s);
        }
        grid_barrier(128);
    }
}

// ---------------- host orchestration ----------------
extern "C" void kernel_launch(void* const* d_in, const int* in_sizes, int n_in,
                              void* d_out, int out_size) {
    const float* u = 0; const float* wa = 0; const float* wb = 0;
    for (int i = 0; i < n_in; i++) {
        if (in_sizes[i] == INDIM * TLEN)       u  = (const float*)d_in[i];
        else if (in_sizes[i] == ORD * ORD)     wa = (const float*)d_in[i];
        else if (in_sizes[i] == ORD * INDIM)   wb = (const float*)d_in[i];
    }
    float* out = (float*)d_out;

    float *E0, *E1, *E2, *E3, *D, *Q2, *Q4, *Q8, *Q16, *S, *Bnd, *part;
    cudaGetSymbolAddress((void**)&E0, g_E0);
    cudaGetSymbolAddress((void**)&E1, g_E1);
    cudaGetSymbolAddress((void**)&E2, g_E2);
    cudaGetSymbolAddress((void**)&E3, g_E3);
    cudaGetSymbolAddress((void**)&D,  g_D);
    cudaGetSymbolAddress((void**)&Q2, g_Q2);
    cudaGetSymbolAddress((void**)&Q4, g_Q4);
    cudaGetSymbolAddress((void**)&Q8, g_Q8);
    cudaGetSymbolAddress((void**)&Q16, g_Q16);
    cudaGetSymbolAddress((void**)&S,  g_S);
    cudaGetSymbolAddress((void**)&Bnd, g_Bnd);
    cudaGetSymbolAddress((void**)&part, g_part);

    // 1) BU tree level 0
    bu_kernel<<<dim3(TLEN / 32, ORD / 8), dim3(32, 8)>>>(wb, u, E0);

    // 2) squarings: A^2, A^4, A^8, A^16
    gemm128<<<dim3(16, 16, 1), 256>>>(wa, wa, ORD, 1, 0, Q2,  ORD, 1, 0,
                                      0, 0, 0, 0, 0, part, 2048, 2048);
    gemm128<<<dim3(16, 16, 1), 256>>>(Q2, Q2, ORD, 1, 0, Q4,  ORD, 1, 0,
                                      0, 0, 0, 0, 0, part, 2048, 2048);
    gemm128<<<dim3(16, 16, 1), 256>>>(Q4, Q4, ORD, 1, 0, Q8,  ORD, 1, 0,
                                      0, 0, 0, 0, 0, part, 2048, 2048);
    gemm128<<<dim3(16, 16, 1), 256>>>(Q8, Q8, ORD, 1, 0, Q16, ORD, 1, 0,
                                      0, 0, 0, 0, 0, part, 2048, 2048);

    // 3) upsweep: E1 = A*E0even + E0odd; E2 = A2*E1even + E1odd; ...
    gemm128<<<dim3(16, 16, 1), 256>>>(wa, E0, 4096, 2, 0, E1, 2048, 1, 0,
                                      E0, 4096, 2, 1, 0, part, 2048, 2048);
    gemm128<<<dim3(8, 16, 1), 256>>>(Q2, E1, 2048, 2, 0, E2, 1024, 1, 0,
                                     E1, 2048, 2, 1, 0, part, 1024, 2048);
    gemm128<<<dim3(4, 16, 2), 256>>>(Q4, E2, 1024, 2, 0, 0, 0, 0, 0,
                                     0, 0, 0, 0, 0, part, 512, 1024);
    reduce_k<<<ORD * 512 / 256, 256>>>(part, 512, 2, E2, 1024, 2, 1,
                                       E3, 512, 1, 0, 0);
    gemm128<<<dim3(2, 16, 4), 256>>>(Q8, E3, 512, 2, 0, 0, 0, 0, 0,
                                     0, 0, 0, 0, 0, part, 256, 512);
    reduce_k<<<ORD * 256 / 256, 256>>>(part, 256, 4, E3, 512, 2, 1,
                                       D, 256, 1, 0, 0);

    // 4) serial boundary scan (emits j=0, fills S block 0 and Bnd)
    scan_kernel<<<128, 256>>>(Q16, D, Bnd, S, out);

    // 5) downsweep: s8 = A8*s0 + E3_0; [s4,s12] = A4*[s0,s8] + [E2_0,E2_2]; ...
    gemm128<<<dim3(2, 16, 4), 256>>>(Q8, Bnd, 256, 1, 0, 0, 0, 0, 0,
                                     0, 0, 0, 0, 0, part, 256, 512);
    reduce_k<<<ORD * 256 / 256, 256>>>(part, 256, 4, E3, 512, 2, 0,
                                       S, 4096, 0, 8, out);
    gemm128<<<dim3(4, 16, 2), 256>>>(Q4, S, 4096, 8, 0, 0, 0, 0, 0,
                                     0, 0, 0, 0, 0, part, 512, 1024);
    reduce_k<<<ORD * 512 / 256, 256>>>(part, 512, 2, E2, 1024, 2, 0,
                                       S, 4096, 8, 4, out);
    gemm128<<<dim3(8, 16, 1), 256>>>(Q2, S, 4096, 4, 0, S, 4096, 4, 2,
                                     E1, 2048, 2, 0, out, part, 1024, 2048);
    gemm128<<<dim3(16, 16, 1), 256>>>(wa, S, 4096, 2, 0, S, 4096, 2, 1,
                                      E0, 4096, 2, 0, out, part, 2048, 2048);
}

// round 6
// speedup vs baseline: 2.0534x; 1.2872x over previous
#include <cuda_runtime.h>
#include <cuda_bf16.h>
#include <math.h>
#include <stdint.h>

#define ORD  2048
#define INDIM 64
#define TLEN 4096
#define NC   256

typedef unsigned long long ull;
typedef __nv_bfloat16 bf16;

// ================= static device scratch (allocation-free) =================
__device__ bf16 g_Ah [ORD*ORD], g_Al [ORD*ORD];   // wa straight
__device__ bf16 g_ATh[ORD*ORD], g_ATl[ORD*ORD];   // wa transposed
__device__ bf16 g_Q2h[ORD*ORD], g_Q2l[ORD*ORD], g_Q2Th[ORD*ORD], g_Q2Tl[ORD*ORD];
__device__ bf16 g_Q4h[ORD*ORD], g_Q4l[ORD*ORD], g_Q4Th[ORD*ORD], g_Q4Tl[ORD*ORD];
__device__ bf16 g_Q8h[ORD*ORD], g_Q8l[ORD*ORD], g_Q8Th[ORD*ORD], g_Q8Tl[ORD*ORD];
__device__ float g_Q16[ORD*ORD];
__device__ float g_E0[ORD*4096];
__device__ bf16 g_E0Th[4096*ORD], g_E0Tl[4096*ORD];
__device__ float g_E1[ORD*2048];
__device__ bf16 g_E1Th[2048*ORD], g_E1Tl[2048*ORD];
__device__ float g_E2[ORD*1024];
__device__ bf16 g_E2Th[1024*ORD], g_E2Tl[1024*ORD];
__device__ float g_E3[ORD*512];
__device__ bf16 g_E3Th[512*ORD], g_E3Tl[512*ORD];
__device__ float g_D[ORD*256];
__device__ bf16 g_STh[4096*ORD], g_STl[4096*ORD];   // states transposed, row=j*256+c
__device__ float g_bv[2 * ORD];
__device__ unsigned int g_bar_count;
__device__ volatile unsigned int g_bar_gen;

// ================= helpers =================
__device__ __forceinline__ uint32_t smem_u32(const void* p) {
    return (uint32_t)__cvta_generic_to_shared(p);
}
// 64B-row swizzle: XOR 16B-group bits [5:4] with row bits (addr bits [8:7])
#define SWZ64(b) ((b) ^ (((b) >> 3) & 0x30))

__device__ __forceinline__ void cp16(uint32_t dst, const void* src) {
    asm volatile("cp.async.cg.shared.global [%0], [%1], 16;" :: "r"(dst), "l"(src));
}
__device__ __forceinline__ void cp_commit() {
    asm volatile("cp.async.commit_group;" ::: "memory");
}

__device__ __forceinline__ void ldm_x4(uint32_t* r, uint32_t addr) {
    asm volatile("ldmatrix.sync.aligned.m8n8.x4.shared.b16 {%0,%1,%2,%3}, [%4];"
        : "=r"(r[0]), "=r"(r[1]), "=r"(r[2]), "=r"(r[3]) : "r"(addr));
}
__device__ __forceinline__ void mma_bf16(float* d, const uint32_t* a, const uint32_t* b) {
    asm volatile(
        "mma.sync.aligned.m16n8k16.row.col.f32.bf16.bf16.f32 "
        "{%0,%1,%2,%3}, {%4,%5,%6,%7}, {%8,%9}, {%0,%1,%2,%3};"
        : "+f"(d[0]), "+f"(d[1]), "+f"(d[2]), "+f"(d[3])
        : "r"(a[0]), "r"(a[1]), "r"(a[2]), "r"(a[3]), "r"(b[0]), "r"(b[1]));
}

// ================= packed f32x2 helpers (scan kernel) =================
__device__ __forceinline__ ull fma2(ull a, ull b, ull c) {
    ull d;
    asm("fma.rn.f32x2 %0, %1, %2, %3;" : "=l"(d) : "l"(a), "l"(b), "l"(c));
    return d;
}
__device__ __forceinline__ float2 unpk(ull v) {
    float2 f;
    asm("mov.b64 {%0, %1}, %2;" : "=f"(f.x), "=f"(f.y) : "l"(v));
    return f;
}

// ================= single-wave spin grid barrier =================
__device__ __forceinline__ void grid_barrier(unsigned int nb) {
    __syncthreads();
    if (threadIdx.x == 0) {
        __threadfence();
        unsigned int gen = g_bar_gen;
        if (atomicAdd(&g_bar_count, 1u) == nb - 1u) {
            g_bar_count = 0u;
            __threadfence();
            g_bar_gen = gen + 1u;
        } else {
            while (g_bar_gen == gen) { __nanosleep(32); }
        }
        __threadfence();
    }
    __syncthreads();
}

// ================= conversion kernels =================
__global__ void conv_straight(const float* __restrict__ src,
                              bf16* __restrict__ h, bf16* __restrict__ l) {
    int idx = blockIdx.x * 256 + threadIdx.x;
    float v = src[idx];
    bf16 hi = __float2bfloat16(v);
    h[idx] = hi;
    l[idx] = __float2bfloat16(v - __bfloat162float(hi));
}

__global__ void conv_transpose(const float* __restrict__ src,
                               bf16* __restrict__ th, bf16* __restrict__ tl) {
    __shared__ float tile[32][33];
    int bx = blockIdx.x * 32, by = blockIdx.y * 32;
    int tx = threadIdx.x;
    for (int i = threadIdx.y; i < 32; i += 8)
        tile[i][tx] = src[(size_t)(by + i) * ORD + bx + tx];
    __syncthreads();
    for (int i = threadIdx.y; i < 32; i += 8) {
        float v = tile[tx][i];                  // = src[by+tx][bx+i]
        bf16 hi = __float2bfloat16(v);
        size_t o = (size_t)(bx + i) * ORD + by + tx;
        th[o] = hi;
        tl[o] = __float2bfloat16(v - __bfloat162float(hi));
    }
}

// ================= BU precompute =================
__global__ void bu_kernel(const float* __restrict__ B, const float* __restrict__ u,
                          float* __restrict__ E0,
                          bf16* __restrict__ E0Th, bf16* __restrict__ E0Tl) {
    int t = blockIdx.x * 32 + threadIdx.x;   // blockDim (32,8)
    int r = blockIdx.y * 8 + threadIdx.y;
    float s = 0.f;
#pragma unroll
    for (int d = 0; d < INDIM; d++)
        s += B[r * INDIM + d] * u[d * TLEN + t];
    size_t col = (size_t)(t & 15) * 256 + (t >> 4);
    E0[(size_t)r * 4096 + col] = s;
    bf16 hi = __float2bfloat16(s);
    E0Th[col * ORD + r] = hi;
    E0Tl[col * ORD + r] = __float2bfloat16(s - __bfloat162float(hi));
}

// ================= mma.sync GEMM =================
// D[m][n] = sum_k A[m][k]*BT[n][k], bf16 3-product split, fp32 accum.
// CTA tile M=128 x N=128. blockIdx.x = 128-col tile; dblk = bx>>1 selects the
// 256-col logical block (R4 semantics), w = (bx&1)*128 offset inside it.
// Epilogue fusions identical to R4's gemm_tc.
#define KC 32
#define STG_B 32768            // Ah 8K | Al 8K | Bh 8K | Bl 8K
#define GEMM_SMEM (4 * STG_B)  // also reused as float Cs[128][132] (67.6 KB)

__device__ __forceinline__ void load_stage(
    uint32_t st, const bf16* __restrict__ Ah, const bf16* __restrict__ Al,
    const bf16* __restrict__ Bh, const bf16* __restrict__ Bl,
    size_t arow0, size_t brow0, size_t kb, int tid)
{
#pragma unroll
    for (int q = 0; q < 2; q++) {
        int ch = tid + q * 256;
        int row = ch >> 2, kg = ch & 3;
        uint32_t b = (uint32_t)(row * 64 + kg * 16);
        uint32_t p = SWZ64(b);
        size_t go = (arow0 + row) * ORD + kb + kg * 8;
        cp16(st + p, Ah + go);
        cp16(st + 8192 + p, Al + go);
    }
#pragma unroll
    for (int q = 0; q < 2; q++) {
        int ch = tid + q * 256;
        int row = ch >> 2, kg = ch & 3;
        uint32_t b = (uint32_t)(row * 64 + kg * 16);
        uint32_t p = SWZ64(b);
        size_t go = (brow0 + row) * ORD + kb + kg * 8;
        cp16(st + 16384 + p, Bh + go);
        cp16(st + 24576 + p, Bl + go);
    }
}

__global__ void __launch_bounds__(256, 1) gemm_mma(
    const bf16* __restrict__ Ah, const bf16* __restrict__ Al,
    const bf16* __restrict__ Bh, const bf16* __restrict__ Bl,
    int bmul, int boff,
    float* __restrict__ C, int ldc,
    bf16* __restrict__ Sh, bf16* __restrict__ Sl,
    bf16* __restrict__ Th, bf16* __restrict__ Tl,
    const float* __restrict__ E, int lde, int amul, int aoff,
    float* __restrict__ outp, int dmul, int doff)
{
    extern __shared__ char smem[];
    uint32_t sb = smem_u32(smem);
    int tid = threadIdx.x, wid = tid >> 5, lane = tid & 31;
    int bm = blockIdx.y * 128;
    int dblk = blockIdx.x >> 1, w = (blockIdx.x & 1) * 128;
    size_t arow0 = (size_t)bm;
    size_t brow0 = (size_t)(bmul * dblk + boff) * 256 + w;
    int wm = wid >> 2, wn = wid & 3;

    float acc[4][4][4];
#pragma unroll
    for (int i = 0; i < 4; i++)
#pragma unroll
        for (int j = 0; j < 4; j++)
#pragma unroll
            for (int k = 0; k < 4; k++) acc[i][j][k] = 0.f;

    // precompute swizzled fragment addresses (stage-relative)
    uint32_t a_off[2][4], b_off[2][2];
#pragma unroll
    for (int k16 = 0; k16 < 2; k16++) {
#pragma unroll
        for (int mt = 0; mt < 4; mt++) {
            int row = wm * 64 + mt * 16 + (lane & 15);
            uint32_t b = (uint32_t)(row * 64 + k16 * 32 + (lane >> 4) * 16);
            a_off[k16][mt] = SWZ64(b);
        }
#pragma unroll
        for (int p = 0; p < 2; p++) {
            int n = wn * 32 + p * 16 + ((lane >> 4) & 1) * 8 + (lane & 7);
            uint32_t b = (uint32_t)(n * 64 + k16 * 32 + ((lane >> 3) & 1) * 16);
            b_off[k16][p] = SWZ64(b);
        }
    }

    // prologue: stages 0..2
#pragma unroll
    for (int s = 0; s < 3; s++) {
        load_stage(sb + s * STG_B, Ah, Al, Bh, Bl, arow0, brow0, (size_t)s * KC, tid);
        cp_commit();
    }

    const int NIT = ORD / KC;   // 64
    for (int t = 0; t < NIT; t++) {
        if (t < NIT - 2)      asm volatile("cp.async.wait_group 2;" ::: "memory");
        else if (t == NIT - 2) asm volatile("cp.async.wait_group 1;" ::: "memory");
        else                   asm volatile("cp.async.wait_group 0;" ::: "memory");
        __syncthreads();

        uint32_t st = sb + (t & 3) * STG_B;
#pragma unroll
        for (int k16 = 0; k16 < 2; k16++) {
            uint32_t ah[4][4], al[4][4], bh[2][4], bl[2][4];
#pragma unroll
            for (int mt = 0; mt < 4; mt++) {
                ldm_x4(ah[mt], st + a_off[k16][mt]);
                ldm_x4(al[mt], st + 8192 + a_off[k16][mt]);
            }
#pragma unroll
            for (int p = 0; p < 2; p++) {
                ldm_x4(bh[p], st + 16384 + b_off[k16][p]);
                ldm_x4(bl[p], st + 24576 + b_off[k16][p]);
            }
#pragma unroll
            for (int mt = 0; mt < 4; mt++)
#pragma unroll
                for (int nt = 0; nt < 4; nt++) {
                    const uint32_t* bhp = &bh[nt >> 1][(nt & 1) * 2];
                    const uint32_t* blp = &bl[nt >> 1][(nt & 1) * 2];
                    mma_bf16(acc[mt][nt], ah[mt], bhp);
                    mma_bf16(acc[mt][nt], ah[mt], blp);
                    mma_bf16(acc[mt][nt], al[mt], bhp);
                }
        }
        __syncthreads();

        if (t + 3 < NIT) {
            load_stage(sb + ((t + 3) & 3) * STG_B, Ah, Al, Bh, Bl,
                       arow0, brow0, (size_t)(t + 3) * KC, tid);
            cp_commit();
        }
    }

    // ---- epilogue: spill accumulators to padded smem ----
    float (*Cs)[132] = (float (*)[132])smem;
#pragma unroll
    for (int mt = 0; mt < 4; mt++)
#pragma unroll
        for (int nt = 0; nt < 4; nt++) {
            int r = wm * 64 + mt * 16 + (lane >> 2);
            int c = wn * 32 + nt * 8 + 2 * (lane & 3);
            *(float2*)&Cs[r][c]     = make_float2(acc[mt][nt][0], acc[mt][nt][1]);
            *(float2*)&Cs[r + 8][c] = make_float2(acc[mt][nt][2], acc[mt][nt][3]);
        }
    __syncthreads();

    int jdst = dmul * dblk + doff;
    // phase A: row-major outputs (2 threads per row, 64 cols each)
    {
        int row = tid >> 1, chb = (tid & 1) * 64;
        int m = bm + row;
#pragma unroll 1
        for (int cb = 0; cb < 4; cb++) {
            int c0 = chb + cb * 16;
            float v[16];
#pragma unroll
            for (int i = 0; i < 16; i++) v[i] = Cs[row][c0 + i];
            if (E) {
                const float* ep = E + (size_t)m * lde
                    + (size_t)(amul * dblk + aoff) * 256 + w + c0;
#pragma unroll
                for (int i = 0; i < 16; i += 4) {
                    float4 e4 = *(const float4*)(ep + i);
                    v[i] += e4.x; v[i+1] += e4.y; v[i+2] += e4.z; v[i+3] += e4.w;
                }
#pragma unroll
                for (int i = 0; i < 16; i++) Cs[row][c0 + i] = v[i];
            }
            if (C) {
                float* cp = C + (size_t)m * ldc + (size_t)jdst * 256 + w + c0;
#pragma unroll
                for (int i = 0; i < 16; i += 4)
                    *(float4*)(cp + i) = make_float4(v[i], v[i+1], v[i+2], v[i+3]);
            }
            if (Sh) {
                bf16* sp = Sh + (size_t)m * ORD + (size_t)jdst * 256 + w + c0;
                bf16* lp = Sl + (size_t)m * ORD + (size_t)jdst * 256 + w + c0;
#pragma unroll
                for (int i = 0; i < 16; i++) {
                    bf16 hi = __float2bfloat16(v[i]);
                    sp[i] = hi;
                    lp[i] = __float2bfloat16(v[i] - __bfloat162float(hi));
                }
            }
            if (outp) {
                float* op = outp + (size_t)m * TLEN + jdst;
#pragma unroll
                for (int i = 0; i < 16; i++)
                    op[(w + c0 + i) * 16] = tanhf(v[i]);
            }
        }
    }
    // phase B: transposed bf16-pair outputs (coalesced via smem transpose read)
    if (Th) {
        __syncthreads();
        int n = tid >> 1, mh = (tid & 1) * 64;
        size_t trow = (size_t)jdst * 256 + w + n;
        bf16* tp = Th + trow * ORD + bm + mh;
        bf16* lp = Tl + trow * ORD + bm + mh;
#pragma unroll 1
        for (int cb = 0; cb < 4; cb++) {
#pragma unroll
            for (int i = 0; i < 16; i++) {
                float vv = Cs[mh + cb * 16 + i][n];
                bf16 hi = __float2bfloat16(vv);
                tp[cb * 16 + i] = hi;
                lp[cb * 16 + i] = __float2bfloat16(vv - __bfloat162float(hi));
            }
        }
    }
}

// ================= persistent boundary scan =================
// b_{c+1} = A16 b_c + D_c. Writes ST block 0 (bf16 pair, row=c, col=r) and tanh at t=c*16.
__global__ void __launch_bounds__(256, 1) scan_kernel(
    const float* __restrict__ A16, const float* __restrict__ D,
    bf16* __restrict__ STh, bf16* __restrict__ STl,
    float* __restrict__ outp)
{
    __shared__ float bs[ORD];
    __shared__ float red[16][9];

    int tid = threadIdx.x;
    int cta = blockIdx.x;                 // 128 CTAs, 16 rows each
    int rloc = tid & 15;
    int row = cta * 16 + rloc;
    int seg = (tid >> 4) * 128;

    ulonglong2 a2[32];
    const ulonglong2* Arow = (const ulonglong2*)(A16 + (size_t)row * ORD + seg);
#pragma unroll
    for (int i = 0; i < 32; i++) a2[i] = Arow[i];

    for (int i = tid; i < ORD; i += 256) g_bv[i] = 1.0f;
    if (tid < 16) {
        int rr = cta * 16 + tid;
        STh[rr] = __float2bfloat16(1.0f);
        STl[rr] = __float2bfloat16(0.0f);
        outp[(size_t)rr * TLEN] = tanhf(1.0f);
    }
    grid_barrier(128);

    for (int c = 0; c < NC - 1; c++) {
        const float4* bsrc = (const float4*)(g_bv + (c & 1) * ORD);
        float4* bdst4 = (float4*)bs;
        bdst4[tid] = bsrc[tid];
        bdst4[tid + 256] = bsrc[tid + 256];
        __syncthreads();

        ull pA = 0ull, pB = 0ull;
        const ulonglong2* b2 = (const ulonglong2*)(bs + seg);
#pragma unroll
        for (int i = 0; i < 32; i++) {
            pA = fma2(a2[i].x, b2[i].x, pA);
            pB = fma2(a2[i].y, b2[i].y, pB);
        }
        float2 fa = unpk(pA), fb = unpk(pB);
        float p = (fa.x + fa.y) + (fb.x + fb.y);
        p += __shfl_down_sync(0xffffffffu, p, 16);
        if ((tid & 31) < 16) red[rloc][tid >> 5] = p;
        __syncthreads();

        if (tid < 16) {
            int rr = cta * 16 + tid;
            float s = red[tid][0] + red[tid][1] + red[tid][2] + red[tid][3]
                    + red[tid][4] + red[tid][5] + red[tid][6] + red[tid][7]
                    + D[(size_t)rr * 256 + c];
            g_bv[((c + 1) & 1) * ORD + rr] = s;
            bf16 hi = __float2bfloat16(s);
            STh[(size_t)(c + 1) * ORD + rr] = hi;
            STl[(size_t)(c + 1) * ORD + rr] = __float2bfloat16(s - __bfloat162float(hi));
            outp[(size_t)rr * TLEN + (c + 1) * 16] = tanhf(s);
        }
        grid_barrier(128);
    }
}

// ================= host orchestration =================
extern "C" void kernel_launch(void* const* d_in, const int* in_sizes, int n_in,
                              void* d_out, int out_size) {
    const float* u = 0; const float* wa = 0; const float* wb = 0;
    for (int i = 0; i < n_in; i++) {
        if (in_sizes[i] == INDIM * TLEN)       u  = (const float*)d_in[i];
        else if (in_sizes[i] == ORD * ORD)     wa = (const float*)d_in[i];
        else if (in_sizes[i] == ORD * INDIM)   wb = (const float*)d_in[i];
    }
    float* out = (float*)d_out;

    bf16 *Ah, *Al, *ATh, *ATl;
    bf16 *Q2h, *Q2l, *Q2Th, *Q2Tl, *Q4h, *Q4l, *Q4Th, *Q4Tl;
    bf16 *Q8h, *Q8l, *Q8Th, *Q8Tl;
    bf16 *E0Th, *E0Tl, *E1Th, *E1Tl, *E2Th, *E2Tl, *E3Th, *E3Tl, *STh, *STl;
    float *Q16, *E0, *E1, *E2, *E3, *Dv;
    cudaGetSymbolAddress((void**)&Ah, g_Ah);   cudaGetSymbolAddress((void**)&Al, g_Al);
    cudaGetSymbolAddress((void**)&ATh, g_ATh); cudaGetSymbolAddress((void**)&ATl, g_ATl);
    cudaGetSymbolAddress((void**)&Q2h, g_Q2h); cudaGetSymbolAddress((void**)&Q2l, g_Q2l);
    cudaGetSymbolAddress((void**)&Q2Th, g_Q2Th); cudaGetSymbolAddress((void**)&Q2Tl, g_Q2Tl);
    cudaGetSymbolAddress((void**)&Q4h, g_Q4h); cudaGetSymbolAddress((void**)&Q4l, g_Q4l);
    cudaGetSymbolAddress((void**)&Q4Th, g_Q4Th); cudaGetSymbolAddress((void**)&Q4Tl, g_Q4Tl);
    cudaGetSymbolAddress((void**)&Q8h, g_Q8h); cudaGetSymbolAddress((void**)&Q8l, g_Q8l);
    cudaGetSymbolAddress((void**)&Q8Th, g_Q8Th); cudaGetSymbolAddress((void**)&Q8Tl, g_Q8Tl);
    cudaGetSymbolAddress((void**)&Q16, g_Q16);
    cudaGetSymbolAddress((void**)&E0, g_E0);
    cudaGetSymbolAddress((void**)&E0Th, g_E0Th); cudaGetSymbolAddress((void**)&E0Tl, g_E0Tl);
    cudaGetSymbolAddress((void**)&E1, g_E1);
    cudaGetSymbolAddress((void**)&E1Th, g_E1Th); cudaGetSymbolAddress((void**)&E1Tl, g_E1Tl);
    cudaGetSymbolAddress((void**)&E2, g_E2);
    cudaGetSymbolAddress((void**)&E2Th, g_E2Th); cudaGetSymbolAddress((void**)&E2Tl, g_E2Tl);
    cudaGetSymbolAddress((void**)&E3, g_E3);
    cudaGetSymbolAddress((void**)&E3Th, g_E3Th); cudaGetSymbolAddress((void**)&E3Tl, g_E3Tl);
    cudaGetSymbolAddress((void**)&Dv, g_D);
    cudaGetSymbolAddress((void**)&STh, g_STh); cudaGetSymbolAddress((void**)&STl, g_STl);

    static int attr_set = 0;
    cudaFuncSetAttribute(gemm_mma, cudaFuncAttributeMaxDynamicSharedMemorySize, GEMM_SMEM);
    (void)attr_set;

    // conversions of wa + BU precompute
    conv_straight<<<ORD * ORD / 256, 256>>>(wa, Ah, Al);
    conv_transpose<<<dim3(64, 64), dim3(32, 8)>>>(wa, ATh, ATl);
    bu_kernel<<<dim3(TLEN / 32, ORD / 8), dim3(32, 8)>>>(wb, u, E0, E0Th, E0Tl);

    // squarings: A^2, A^4, A^8, A^16
    gemm_mma<<<dim3(16, 16), 256, GEMM_SMEM>>>(Ah, Al, ATh, ATl, 1, 0,
        0, 0, Q2h, Q2l, Q2Th, Q2Tl, 0, 0, 0, 0, 0, 1, 0);
    gemm_mma<<<dim3(16, 16), 256, GEMM_SMEM>>>(Q2h, Q2l, Q2Th, Q2Tl, 1, 0,
        0, 0, Q4h, Q4l, Q4Th, Q4Tl, 0, 0, 0, 0, 0, 1, 0);
    gemm_mma<<<dim3(16, 16), 256, GEMM_SMEM>>>(Q4h, Q4l, Q4Th, Q4Tl, 1, 0,
        0, 0, Q8h, Q8l, Q8Th, Q8Tl, 0, 0, 0, 0, 0, 1, 0);
    gemm_mma<<<dim3(16, 16), 256, GEMM_SMEM>>>(Q8h, Q8l, Q8Th, Q8Tl, 1, 0,
        Q16, ORD, 0, 0, 0, 0, 0, 0, 0, 0, 0, 1, 0);

    // upsweep
    gemm_mma<<<dim3(16, 16), 256, GEMM_SMEM>>>(Ah, Al, E0Th, E0Tl, 2, 0,
        E1, 2048, 0, 0, E1Th, E1Tl, E0, 4096, 2, 1, 0, 1, 0);
    gemm_mma<<<dim3(8, 16), 256, GEMM_SMEM>>>(Q2h, Q2l, E1Th, E1Tl, 2, 0,
        E2, 1024, 0, 0, E2Th, E2Tl, E1, 2048, 2, 1, 0, 1, 0);
    gemm_mma<<<dim3(4, 16), 256, GEMM_SMEM>>>(Q4h, Q4l, E2Th, E2Tl, 2, 0,
        E3, 512, 0, 0, E3Th, E3Tl, E2, 1024, 2, 1, 0, 1, 0);
    gemm_mma<<<dim3(2, 16), 256, GEMM_SMEM>>>(Q8h, Q8l, E3Th, E3Tl, 2, 0,
        Dv, 256, 0, 0, 0, 0, E3, 512, 2, 1, 0, 1, 0);

    // serial boundary scan (emits j=0, fills ST block 0)
    scan_kernel<<<128, 256>>>(Q16, Dv, STh, STl, out);

    // downsweep
    gemm_mma<<<dim3(2, 16), 256, GEMM_SMEM>>>(Q8h, Q8l, STh, STl, 1, 0,
        0, 0, 0, 0, STh, STl, E3, 512, 2, 0, out, 0, 8);
    gemm_mma<<<dim3(4, 16), 256, GEMM_SMEM>>>(Q4h, Q4l, STh, STl, 8, 0,
        0, 0, 0, 0, STh, STl, E2, 1024, 2, 0, out, 8, 4);
    gemm_mma<<<dim3(8, 16), 256, GEMM_SMEM>>>(Q2h, Q2l, STh, STl, 4, 0,
        0, 0, 0, 0, STh, STl, E1, 2048, 2, 0, out, 4, 2);
    gemm_mma<<<dim3(16, 16), 256, GEMM_SMEM>>>(Ah, Al, STh, STl, 2, 0,
        0, 0, 0, 0, 0, 0, E0, 4096, 2, 0, out, 2, 1);
}

// round 7
// speedup vs baseline: 2.0675x; 1.0069x over previous
#include <cuda_runtime.h>
#include <cuda_bf16.h>
#include <math.h>
#include <stdint.h>

#define ORD  2048
#define INDIM 64
#define TLEN 4096
#define NC   256

typedef unsigned long long ull;
typedef __nv_bfloat16 bf16;

// ================= static device scratch (allocation-free) =================
__device__ bf16 g_Ah [ORD*ORD], g_Al [ORD*ORD];   // wa straight
__device__ bf16 g_ATh[ORD*ORD], g_ATl[ORD*ORD];   // wa transposed
__device__ bf16 g_Q2h[ORD*ORD], g_Q2l[ORD*ORD], g_Q2Th[ORD*ORD], g_Q2Tl[ORD*ORD];
__device__ bf16 g_Q4h[ORD*ORD], g_Q4l[ORD*ORD], g_Q4Th[ORD*ORD], g_Q4Tl[ORD*ORD];
__device__ bf16 g_Q8h[ORD*ORD], g_Q8l[ORD*ORD], g_Q8Th[ORD*ORD], g_Q8Tl[ORD*ORD];
__device__ float g_Q16[ORD*ORD];
__device__ float g_E0[ORD*4096];
__device__ bf16 g_E0Th[4096*ORD], g_E0Tl[4096*ORD];
__device__ float g_E1[ORD*2048];
__device__ bf16 g_E1Th[2048*ORD], g_E1Tl[2048*ORD];
__device__ float g_E2[ORD*1024];
__device__ bf16 g_E2Th[1024*ORD], g_E2Tl[1024*ORD];
__device__ float g_E3[ORD*512];
__device__ bf16 g_E3Th[512*ORD], g_E3Tl[512*ORD];
__device__ float g_D[ORD*256];
__device__ bf16 g_STh[4096*ORD], g_STl[4096*ORD];   // states transposed, row=j*256+c
__device__ float g_bv[2 * ORD];
__device__ unsigned int g_bar_count;
__device__ volatile unsigned int g_bar_gen;

// ================= helpers =================
__device__ __forceinline__ uint32_t smem_u32(const void* p) {
    return (uint32_t)__cvta_generic_to_shared(p);
}
// 64B-row swizzle: XOR 16B-group bits [5:4] with row bits (addr bits [8:7])
#define SWZ64(b) ((b) ^ (((b) >> 3) & 0x30))

__device__ __forceinline__ void cp16(uint32_t dst, const void* src) {
    asm volatile("cp.async.cg.shared.global [%0], [%1], 16;" :: "r"(dst), "l"(src));
}
__device__ __forceinline__ void cp_commit() {
    asm volatile("cp.async.commit_group;" ::: "memory");
}

__device__ __forceinline__ void ldm_x4(uint32_t* r, uint32_t addr) {
    asm volatile("ldmatrix.sync.aligned.m8n8.x4.shared.b16 {%0,%1,%2,%3}, [%4];"
        : "=r"(r[0]), "=r"(r[1]), "=r"(r[2]), "=r"(r[3]) : "r"(addr));
}
__device__ __forceinline__ void mma_bf16(float* d, const uint32_t* a, const uint32_t* b) {
    asm volatile(
        "mma.sync.aligned.m16n8k16.row.col.f32.bf16.bf16.f32 "
        "{%0,%1,%2,%3}, {%4,%5,%6,%7}, {%8,%9}, {%0,%1,%2,%3};"
        : "+f"(d[0]), "+f"(d[1]), "+f"(d[2]), "+f"(d[3])
        : "r"(a[0]), "r"(a[1]), "r"(a[2]), "r"(a[3]), "r"(b[0]), "r"(b[1]));
}

// ================= packed f32x2 helpers (scan kernel) =================
__device__ __forceinline__ ull fma2(ull a, ull b, ull c) {
    ull d;
    asm("fma.rn.f32x2 %0, %1, %2, %3;" : "=l"(d) : "l"(a), "l"(b), "l"(c));
    return d;
}
__device__ __forceinline__ float2 unpk(ull v) {
    float2 f;
    asm("mov.b64 {%0, %1}, %2;" : "=f"(f.x), "=f"(f.y) : "l"(v));
    return f;
}

// ================= single-wave spin grid barrier =================
__device__ __forceinline__ void grid_barrier(unsigned int nb) {
    __syncthreads();
    if (threadIdx.x == 0) {
        __threadfence();
        unsigned int gen = g_bar_gen;
        if (atomicAdd(&g_bar_count, 1u) == nb - 1u) {
            g_bar_count = 0u;
            __threadfence();
            g_bar_gen = gen + 1u;
        } else {
            while (g_bar_gen == gen) { __nanosleep(32); }
        }
        __threadfence();
    }
    __syncthreads();
}

// ================= conversion kernels =================
__global__ void conv_straight(const float* __restrict__ src,
                              bf16* __restrict__ h, bf16* __restrict__ l) {
    int idx = blockIdx.x * 256 + threadIdx.x;
    float v = src[idx];
    bf16 hi = __float2bfloat16(v);
    h[idx] = hi;
    l[idx] = __float2bfloat16(v - __bfloat162float(hi));
}

__global__ void conv_transpose(const float* __restrict__ src,
                               bf16* __restrict__ th, bf16* __restrict__ tl) {
    __shared__ float tile[32][33];
    int bx = blockIdx.x * 32, by = blockIdx.y * 32;
    int tx = threadIdx.x;
    for (int i = threadIdx.y; i < 32; i += 8)
        tile[i][tx] = src[(size_t)(by + i) * ORD + bx + tx];
    __syncthreads();
    for (int i = threadIdx.y; i < 32; i += 8) {
        float v = tile[tx][i];                  // = src[by+tx][bx+i]
        bf16 hi = __float2bfloat16(v);
        size_t o = (size_t)(bx + i) * ORD + by + tx;
        th[o] = hi;
        tl[o] = __float2bfloat16(v - __bfloat162float(hi));
    }
}

// ================= BU precompute =================
__global__ void bu_kernel(const float* __restrict__ B, const float* __restrict__ u,
                          float* __restrict__ E0,
                          bf16* __restrict__ E0Th, bf16* __restrict__ E0Tl) {
    int t = blockIdx.x * 32 + threadIdx.x;   // blockDim (32,8)
    int r = blockIdx.y * 8 + threadIdx.y;
    float s = 0.f;
#pragma unroll
    for (int d = 0; d < INDIM; d++)
        s += B[r * INDIM + d] * u[d * TLEN + t];
    size_t col = (size_t)(t & 15) * 256 + (t >> 4);
    E0[(size_t)r * 4096 + col] = s;
    bf16 hi = __float2bfloat16(s);
    E0Th[col * ORD + r] = hi;
    E0Tl[col * ORD + r] = __float2bfloat16(s - __bfloat162float(hi));
}

// ================= mma.sync GEMM =================
// D[m][n] = sum_k A[m][k]*BT[n][k], bf16 3-product split, fp32 accum.
// CTA tile M=128 x N=128, 3-stage cp.async pipeline, ONE sync per iter,
// 2 CTAs/SM for latency hiding. Epilogue fusions unchanged.
#define KC 32
#define STG_B 32768            // Ah 8K | Al 8K | Bh 8K | Bl 8K
#define NSTG 3
#define GEMM_SMEM (NSTG * STG_B)  // 96KB; also reused as float Cs[128][132] (67.6 KB)

__device__ __forceinline__ void load_stage(
    uint32_t st, const bf16* __restrict__ Ah, const bf16* __restrict__ Al,
    const bf16* __restrict__ Bh, const bf16* __restrict__ Bl,
    size_t arow0, size_t brow0, size_t kb, int tid)
{
#pragma unroll
    for (int q = 0; q < 2; q++) {
        int ch = tid + q * 256;
        int row = ch >> 2, kg = ch & 3;
        uint32_t b = (uint32_t)(row * 64 + kg * 16);
        uint32_t p = SWZ64(b);
        size_t go = (arow0 + row) * ORD + kb + kg * 8;
        cp16(st + p, Ah + go);
        cp16(st + 8192 + p, Al + go);
    }
#pragma unroll
    for (int q = 0; q < 2; q++) {
        int ch = tid + q * 256;
        int row = ch >> 2, kg = ch & 3;
        uint32_t b = (uint32_t)(row * 64 + kg * 16);
        uint32_t p = SWZ64(b);
        size_t go = (brow0 + row) * ORD + kb + kg * 8;
        cp16(st + 16384 + p, Bh + go);
        cp16(st + 24576 + p, Bl + go);
    }
}

__global__ void __launch_bounds__(256, 2) gemm_mma(
    const bf16* __restrict__ Ah, const bf16* __restrict__ Al,
    const bf16* __restrict__ Bh, const bf16* __restrict__ Bl,
    int bmul, int boff,
    float* __restrict__ C, int ldc,
    bf16* __restrict__ Sh, bf16* __restrict__ Sl,
    bf16* __restrict__ Th, bf16* __restrict__ Tl,
    const float* __restrict__ E, int lde, int amul, int aoff,
    float* __restrict__ outp, int dmul, int doff)
{
    extern __shared__ char smem[];
    uint32_t sb = smem_u32(smem);
    int tid = threadIdx.x, wid = tid >> 5, lane = tid & 31;
    int bm = blockIdx.y * 128;
    int dblk = blockIdx.x >> 1, w = (blockIdx.x & 1) * 128;
    size_t arow0 = (size_t)bm;
    size_t brow0 = (size_t)(bmul * dblk + boff) * 256 + w;
    int wm = wid >> 2, wn = wid & 3;

    float acc[4][4][4];
#pragma unroll
    for (int i = 0; i < 4; i++)
#pragma unroll
        for (int j = 0; j < 4; j++)
#pragma unroll
            for (int k = 0; k < 4; k++) acc[i][j][k] = 0.f;

    // precompute swizzled fragment addresses (stage-relative)
    uint32_t a_off[2][4], b_off[2][2];
#pragma unroll
    for (int k16 = 0; k16 < 2; k16++) {
#pragma unroll
        for (int mt = 0; mt < 4; mt++) {
            int row = wm * 64 + mt * 16 + (lane & 15);
            uint32_t b = (uint32_t)(row * 64 + k16 * 32 + (lane >> 4) * 16);
            a_off[k16][mt] = SWZ64(b);
        }
#pragma unroll
        for (int p = 0; p < 2; p++) {
            int n = wn * 32 + p * 16 + ((lane >> 4) & 1) * 8 + (lane & 7);
            uint32_t b = (uint32_t)(n * 64 + k16 * 32 + ((lane >> 3) & 1) * 16);
            b_off[k16][p] = SWZ64(b);
        }
    }

    // prologue: stages 0..1
#pragma unroll
    for (int s = 0; s < NSTG - 1; s++) {
        load_stage(sb + s * STG_B, Ah, Al, Bh, Bl, arow0, brow0, (size_t)s * KC, tid);
        cp_commit();
    }

    const int NIT = ORD / KC;   // 64
    int stage = 0;
    for (int t = 0; t < NIT; t++) {
        if (t < NIT - 1) asm volatile("cp.async.wait_group 1;" ::: "memory");
        else             asm volatile("cp.async.wait_group 0;" ::: "memory");
        __syncthreads();

        // issue next stage loads immediately (slot was consumed at iter t-1)
        if (t + NSTG - 1 < NIT) {
            int ns = stage + NSTG - 1; if (ns >= NSTG) ns -= NSTG;
            load_stage(sb + ns * STG_B, Ah, Al, Bh, Bl,
                       arow0, brow0, (size_t)(t + NSTG - 1) * KC, tid);
            cp_commit();
        }

        uint32_t st = sb + stage * STG_B;
#pragma unroll
        for (int k16 = 0; k16 < 2; k16++) {
            uint32_t ah[4][4], al[4][4], bh[2][4], bl[2][4];
#pragma unroll
            for (int mt = 0; mt < 4; mt++) {
                ldm_x4(ah[mt], st + a_off[k16][mt]);
                ldm_x4(al[mt], st + 8192 + a_off[k16][mt]);
            }
#pragma unroll
            for (int p = 0; p < 2; p++) {
                ldm_x4(bh[p], st + 16384 + b_off[k16][p]);
                ldm_x4(bl[p], st + 24576 + b_off[k16][p]);
            }
#pragma unroll
            for (int mt = 0; mt < 4; mt++)
#pragma unroll
                for (int nt = 0; nt < 4; nt++) {
                    const uint32_t* bhp = &bh[nt >> 1][(nt & 1) * 2];
                    const uint32_t* blp = &bl[nt >> 1][(nt & 1) * 2];
                    mma_bf16(acc[mt][nt], ah[mt], bhp);
                    mma_bf16(acc[mt][nt], ah[mt], blp);
                    mma_bf16(acc[mt][nt], al[mt], bhp);
                }
        }
        stage++; if (stage >= NSTG) stage = 0;
    }
    __syncthreads();   // all MMAs done before smem reuse as Cs

    // ---- epilogue: spill accumulators to padded smem ----
    float (*Cs)[132] = (float (*)[132])smem;
#pragma unroll
    for (int mt = 0; mt < 4; mt++)
#pragma unroll
        for (int nt = 0; nt < 4; nt++) {
            int r = wm * 64 + mt * 16 + (lane >> 2);
            int c = wn * 32 + nt * 8 + 2 * (lane & 3);
            *(float2*)&Cs[r][c]     = make_float2(acc[mt][nt][0], acc[mt][nt][1]);
            *(float2*)&Cs[r + 8][c] = make_float2(acc[mt][nt][2], acc[mt][nt][3]);
        }
    __syncthreads();

    int jdst = dmul * dblk + doff;
    // phase A: row-major outputs (2 threads per row, 64 cols each)
    {
        int row = tid >> 1, chb = (tid & 1) * 64;
        int m = bm + row;
#pragma unroll 1
        for (int cb = 0; cb < 4; cb++) {
            int c0 = chb + cb * 16;
            float v[16];
#pragma unroll
            for (int i = 0; i < 16; i++) v[i] = Cs[row][c0 + i];
            if (E) {
                const float* ep = E + (size_t)m * lde
                    + (size_t)(amul * dblk + aoff) * 256 + w + c0;
#pragma unroll
                for (int i = 0; i < 16; i += 4) {
                    float4 e4 = *(const float4*)(ep + i);
                    v[i] += e4.x; v[i+1] += e4.y; v[i+2] += e4.z; v[i+3] += e4.w;
                }
#pragma unroll
                for (int i = 0; i < 16; i++) Cs[row][c0 + i] = v[i];
            }
            if (C) {
                float* cp = C + (size_t)m * ldc + (size_t)jdst * 256 + w + c0;
#pragma unroll
                for (int i = 0; i < 16; i += 4)
                    *(float4*)(cp + i) = make_float4(v[i], v[i+1], v[i+2], v[i+3]);
            }
            if (Sh) {
                bf16* sp = Sh + (size_t)m * ORD + (size_t)jdst * 256 + w + c0;
                bf16* lp = Sl + (size_t)m * ORD + (size_t)jdst * 256 + w + c0;
#pragma unroll
                for (int i = 0; i < 16; i++) {
                    bf16 hi = __float2bfloat16(v[i]);
                    sp[i] = hi;
                    lp[i] = __float2bfloat16(v[i] - __bfloat162float(hi));
                }
            }
            if (outp) {
                float* op = outp + (size_t)m * TLEN + jdst;
#pragma unroll
                for (int i = 0; i < 16; i++)
                    op[(w + c0 + i) * 16] = tanhf(v[i]);
            }
        }
    }
    // phase B: transposed bf16-pair outputs (coalesced via smem transpose read)
    if (Th) {
        __syncthreads();
        int n = tid >> 1, mh = (tid & 1) * 64;
        size_t trow = (size_t)jdst * 256 + w + n;
        bf16* tp = Th + trow * ORD + bm + mh;
        bf16* lp = Tl + trow * ORD + bm + mh;
#pragma unroll 1
        for (int cb = 0; cb < 4; cb++) {
#pragma unroll
            for (int i = 0; i < 16; i++) {
                float vv = Cs[mh + cb * 16 + i][n];
                bf16 hi = __float2bfloat16(vv);
                tp[cb * 16 + i] = hi;
                lp[cb * 16 + i] = __float2bfloat16(vv - __bfloat162float(hi));
            }
        }
    }
}

// ================= persistent boundary scan =================
// b_{c+1} = A16 b_c + D_c. Writes ST block 0 (bf16 pair, row=c, col=r) and tanh at t=c*16.
__global__ void __launch_bounds__(256, 1) scan_kernel(
    const float* __restrict__ A16, const float* __restrict__ D,
    bf16* __restrict__ STh, bf16* __restrict__ STl,
    float* __restrict__ outp)
{
    __shared__ float bs[ORD];
    __shared__ float red[16][9];

    int tid = threadIdx.x;
    int cta = blockIdx.x;                 // 128 CTAs, 16 rows each
    int rloc = tid & 15;
    int row = cta * 16 + rloc;
    int seg = (tid >> 4) * 128;

    ulonglong2 a2[32];
    const ulonglong2* Arow = (const ulonglong2*)(A16 + (size_t)row * ORD + seg);
#pragma unroll
    for (int i = 0; i < 32; i++) a2[i] = Arow[i];

    for (int i = tid; i < ORD; i += 256) g_bv[i] = 1.0f;
    if (tid < 16) {
        int rr = cta * 16 + tid;
        STh[rr] = __float2bfloat16(1.0f);
        STl[rr] = __float2bfloat16(0.0f);
        outp[(size_t)rr * TLEN] = tanhf(1.0f);
    }
    grid_barrier(128);

    for (int c = 0; c < NC - 1; c++) {
        const float4* bsrc = (const float4*)(g_bv + (c & 1) * ORD);
        float4* bdst4 = (float4*)bs;
        bdst4[tid] = bsrc[tid];
        bdst4[tid + 256] = bsrc[tid + 256];
        __syncthreads();

        ull pA = 0ull, pB = 0ull;
        const ulonglong2* b2 = (const ulonglong2*)(bs + seg);
#pragma unroll
        for (int i = 0; i < 32; i++) {
            pA = fma2(a2[i].x, b2[i].x, pA);
            pB = fma2(a2[i].y, b2[i].y, pB);
        }
        float2 fa = unpk(pA), fb = unpk(pB);
        float p = (fa.x + fa.y) + (fb.x + fb.y);
        p += __shfl_down_sync(0xffffffffu, p, 16);
        if ((tid & 31) < 16) red[rloc][tid >> 5] = p;
        __syncthreads();

        if (tid < 16) {
            int rr = cta * 16 + tid;
            float s = red[tid][0] + red[tid][1] + red[tid][2] + red[tid][3]
                    + red[tid][4] + red[tid][5] + red[tid][6] + red[tid][7]
                    + D[(size_t)rr * 256 + c];
            g_bv[((c + 1) & 1) * ORD + rr] = s;
            bf16 hi = __float2bfloat16(s);
            STh[(size_t)(c + 1) * ORD + rr] = hi;
            STl[(size_t)(c + 1) * ORD + rr] = __float2bfloat16(s - __bfloat162float(hi));
            outp[(size_t)rr * TLEN + (c + 1) * 16] = tanhf(s);
        }
        grid_barrier(128);
    }
}

// ================= host orchestration =================
extern "C" void kernel_launch(void* const* d_in, const int* in_sizes, int n_in,
                              void* d_out, int out_size) {
    const float* u = 0; const float* wa = 0; const float* wb = 0;
    for (int i = 0; i < n_in; i++) {
        if (in_sizes[i] == INDIM * TLEN)       u  = (const float*)d_in[i];
        else if (in_sizes[i] == ORD * ORD)     wa = (const float*)d_in[i];
        else if (in_sizes[i] == ORD * INDIM)   wb = (const float*)d_in[i];
    }
    float* out = (float*)d_out;

    bf16 *Ah, *Al, *ATh, *ATl;
    bf16 *Q2h, *Q2l, *Q2Th, *Q2Tl, *Q4h, *Q4l, *Q4Th, *Q4Tl;
    bf16 *Q8h, *Q8l, *Q8Th, *Q8Tl;
    bf16 *E0Th, *E0Tl, *E1Th, *E1Tl, *E2Th, *E2Tl, *E3Th, *E3Tl, *STh, *STl;
    float *Q16, *E0, *E1, *E2, *E3, *Dv;
    cudaGetSymbolAddress((void**)&Ah, g_Ah);   cudaGetSymbolAddress((void**)&Al, g_Al);
    cudaGetSymbolAddress((void**)&ATh, g_ATh); cudaGetSymbolAddress((void**)&ATl, g_ATl);
    cudaGetSymbolAddress((void**)&Q2h, g_Q2h); cudaGetSymbolAddress((void**)&Q2l, g_Q2l);
    cudaGetSymbolAddress((void**)&Q2Th, g_Q2Th); cudaGetSymbolAddress((void**)&Q2Tl, g_Q2Tl);
    cudaGetSymbolAddress((void**)&Q4h, g_Q4h); cudaGetSymbolAddress((void**)&Q4l, g_Q4l);
    cudaGetSymbolAddress((void**)&Q4Th, g_Q4Th); cudaGetSymbolAddress((void**)&Q4Tl, g_Q4Tl);
    cudaGetSymbolAddress((void**)&Q8h, g_Q8h); cudaGetSymbolAddress((void**)&Q8l, g_Q8l);
    cudaGetSymbolAddress((void**)&Q8Th, g_Q8Th); cudaGetSymbolAddress((void**)&Q8Tl, g_Q8Tl);
    cudaGetSymbolAddress((void**)&Q16, g_Q16);
    cudaGetSymbolAddress((void**)&E0, g_E0);
    cudaGetSymbolAddress((void**)&E0Th, g_E0Th); cudaGetSymbolAddress((void**)&E0Tl, g_E0Tl);
    cudaGetSymbolAddress((void**)&E1, g_E1);
    cudaGetSymbolAddress((void**)&E1Th, g_E1Th); cudaGetSymbolAddress((void**)&E1Tl, g_E1Tl);
    cudaGetSymbolAddress((void**)&E2, g_E2);
    cudaGetSymbolAddress((void**)&E2Th, g_E2Th); cudaGetSymbolAddress((void**)&E2Tl, g_E2Tl);
    cudaGetSymbolAddress((void**)&E3, g_E3);
    cudaGetSymbolAddress((void**)&E3Th, g_E3Th); cudaGetSymbolAddress((void**)&E3Tl, g_E3Tl);
    cudaGetSymbolAddress((void**)&Dv, g_D);
    cudaGetSymbolAddress((void**)&STh, g_STh); cudaGetSymbolAddress((void**)&STl, g_STl);

    cudaFuncSetAttribute(gemm_mma, cudaFuncAttributeMaxDynamicSharedMemorySize, GEMM_SMEM);

    // conversions of wa + BU precompute
    conv_straight<<<ORD * ORD / 256, 256>>>(wa, Ah, Al);
    conv_transpose<<<dim3(64, 64), dim3(32, 8)>>>(wa, ATh, ATl);
    bu_kernel<<<dim3(TLEN / 32, ORD / 8), dim3(32, 8)>>>(wb, u, E0, E0Th, E0Tl);

    // squarings: A^2, A^4, A^8, A^16
    gemm_mma<<<dim3(16, 16), 256, GEMM_SMEM>>>(Ah, Al, ATh, ATl, 1, 0,
        0, 0, Q2h, Q2l, Q2Th, Q2Tl, 0, 0, 0, 0, 0, 1, 0);
    gemm_mma<<<dim3(16, 16), 256, GEMM_SMEM>>>(Q2h, Q2l, Q2Th, Q2Tl, 1, 0,
        0, 0, Q4h, Q4l, Q4Th, Q4Tl, 0, 0, 0, 0, 0, 1, 0);
    gemm_mma<<<dim3(16, 16), 256, GEMM_SMEM>>>(Q4h, Q4l, Q4Th, Q4Tl, 1, 0,
        0, 0, Q8h, Q8l, Q8Th, Q8Tl, 0, 0, 0, 0, 0, 1, 0);
    gemm_mma<<<dim3(16, 16), 256, GEMM_SMEM>>>(Q8h, Q8l, Q8Th, Q8Tl, 1, 0,
        Q16, ORD, 0, 0, 0, 0, 0, 0, 0, 0, 0, 1, 0);

    // upsweep
    gemm_mma<<<dim3(16, 16), 256, GEMM_SMEM>>>(Ah, Al, E0Th, E0Tl, 2, 0,
        E1, 2048, 0, 0, E1Th, E1Tl, E0, 4096, 2, 1, 0, 1, 0);
    gemm_mma<<<dim3(8, 16), 256, GEMM_SMEM>>>(Q2h, Q2l, E1Th, E1Tl, 2, 0,
        E2, 1024, 0, 0, E2Th, E2Tl, E1, 2048, 2, 1, 0, 1, 0);
    gemm_mma<<<dim3(4, 16), 256, GEMM_SMEM>>>(Q4h, Q4l, E2Th, E2Tl, 2, 0,
        E3, 512, 0, 0, E3Th, E3Tl, E2, 1024, 2, 1, 0, 1, 0);
    gemm_mma<<<dim3(2, 16), 256, GEMM_SMEM>>>(Q8h, Q8l, E3Th, E3Tl, 2, 0,
        Dv, 256, 0, 0, 0, 0, E3, 512, 2, 1, 0, 1, 0);

    // serial boundary scan (emits j=0, fills ST block 0)
    scan_kernel<<<128, 256>>>(Q16, Dv, STh, STl, out);

    // downsweep
    gemm_mma<<<dim3(2, 16), 256, GEMM_SMEM>>>(Q8h, Q8l, STh, STl, 1, 0,
        0, 0, 0, 0, STh, STl, E3, 512, 2, 0, out, 0, 8);
    gemm_mma<<<dim3(4, 16), 256, GEMM_SMEM>>>(Q4h, Q4l, STh, STl, 8, 0,
        0, 0, 0, 0, STh, STl, E2, 1024, 2, 0, out, 8, 4);
    gemm_mma<<<dim3(8, 16), 256, GEMM_SMEM>>>(Q2h, Q2l, STh, STl, 4, 0,
        0, 0, 0, 0, STh, STl, E1, 2048, 2, 0, out, 4, 2);
    gemm_mma<<<dim3(16, 16), 256, GEMM_SMEM>>>(Ah, Al, STh, STl, 2, 0,
        0, 0, 0, 0, 0, 0, E0, 4096, 2, 0, out, 2, 1);
}